// round 12
// baseline (speedup 1.0000x reference)
#include <cuda_runtime.h>
#include <stdint.h>

#define D 128
#define MAX_NODES 100000
#define MAX_EDGES 1700000
#define NSM 148
#define GBM 128
#define AST 129
#define ASZ (D * AST)
#define BSHIFT 3                         // 8 src rows per bucket
#define MAX_NB ((131072 >> BSHIFT) + 2)

__device__ float g_y[MAX_NODES * D];     // 51.2 MB
__device__ int   g_bad;
__device__ int   g_hist[MAX_NB];
__device__ int   g_start[MAX_NB];        // exclusive scan (stable)
__device__ int   g_cursor[MAX_NB];       // scatter cursors
__device__ int4  g_sorted[MAX_EDGES];    // (src, dst, eid, 0)

// ---------------------------------------------------------------------------
__device__ __forceinline__ void ldg_el32B(const float* p, float4& lo, float4& hi) {
    unsigned long long x0, x1, x2, x3;
    asm volatile("ld.global.nc.L2::evict_last.v4.b64 {%0,%1,%2,%3}, [%4];"
                 : "=l"(x0), "=l"(x1), "=l"(x2), "=l"(x3) : "l"(p));
    lo.x = __uint_as_float((unsigned)x0); lo.y = __uint_as_float((unsigned)(x0 >> 32));
    lo.z = __uint_as_float((unsigned)x1); lo.w = __uint_as_float((unsigned)(x1 >> 32));
    hi.x = __uint_as_float((unsigned)x2); hi.y = __uint_as_float((unsigned)(x2 >> 32));
    hi.z = __uint_as_float((unsigned)x3); hi.w = __uint_as_float((unsigned)(x3 >> 32));
}
__device__ __forceinline__ void stg_el32B(float* p, unsigned long long x0,
                                          unsigned long long x1,
                                          unsigned long long x2,
                                          unsigned long long x3) {
    asm volatile("st.global.L2::evict_last.v4.b64 [%0], {%1,%2,%3,%4};"
                 :: "l"(p), "l"(x0), "l"(x1), "l"(x2), "l"(x3) : "memory");
}
__device__ __forceinline__ void cp_async4(uint32_t smem_addr, const float* gptr) {
    asm volatile("cp.async.ca.shared.global [%0], [%1], 4;"
                 :: "r"(smem_addr), "l"(gptr));
}

// ---------------------------------------------------------------------------
// K0: zero hist + detect dtype
// ---------------------------------------------------------------------------
__global__ void init_k(const unsigned int* __restrict__ ei_raw, int nwords, int nb)
{
    int gt = blockIdx.x * blockDim.x + threadIdx.x;
    for (int i = gt; i < nb + 1; i += gridDim.x * blockDim.x)
        g_hist[i] = 0;
    if (blockIdx.x == 0) {
        __shared__ int bad;
        if (threadIdx.x == 0) bad = 0;
        __syncthreads();
        int limit = 1024;
        if (limit > nwords) limit = nwords & ~1;
        for (int i = threadIdx.x; i * 2 + 1 < limit; i += blockDim.x)
            if (ei_raw[i * 2 + 1] != 0u) atomicOr(&bad, 1);
        __syncthreads();
        if (threadIdx.x == 0) g_bad = bad;
    }
}

// K1: bucket histogram
__global__ void hist_k(const void* __restrict__ ei, int E)
{
    const int bad = g_bad;
    int gt = blockIdx.x * blockDim.x + threadIdx.x;
    int stride = gridDim.x * blockDim.x;
    for (int e = gt; e < E; e += stride) {
        int s = bad ? ((const int*)ei)[e]
                    : (int)((const long long*)ei)[e];
        atomicAdd(&g_hist[s >> BSHIFT], 1);
    }
}

// K2: exclusive scan over nb buckets (single block) -> g_start, g_cursor
__global__ void __launch_bounds__(1024) scan_k(int nb, int E)
{
    __shared__ int part[1024];
    const int tid = threadIdx.x;
    const int chunk = (nb + 1023) >> 10;
    int lo = tid * chunk;
    int hi = lo + chunk; if (hi > nb) hi = nb; if (lo > nb) lo = nb;

    int s = 0;
    for (int i = lo; i < hi; i++) s += g_hist[i];
    part[tid] = s;
    __syncthreads();
    #pragma unroll
    for (int off = 1; off < 1024; off <<= 1) {
        int v = (tid >= off) ? part[tid - off] : 0;
        __syncthreads();
        part[tid] += v;
        __syncthreads();
    }
    int run = part[tid] - s;
    for (int i = lo; i < hi; i++) {
        g_start[i]  = run;
        g_cursor[i] = run;
        run += g_hist[i];
    }
    if (tid == 1023) g_start[nb] = E;
}

// K3: scatter edges into bucket order
__global__ void scatter_k(const void* __restrict__ ei, int E)
{
    const int bad = g_bad;
    int gt = blockIdx.x * blockDim.x + threadIdx.x;
    int stride = gridDim.x * blockDim.x;
    for (int e = gt; e < E; e += stride) {
        int s, d;
        if (bad) {
            const int* p = (const int*)ei;
            s = p[e]; d = p[E + e];
        } else {
            const long long* p = (const long long*)ei;
            s = (int)p[e]; d = (int)p[(long long)E + e];
        }
        int pos = atomicAdd(&g_cursor[s >> BSHIFT], 1);
        g_sorted[pos] = make_int4(s, d, e, 0);
    }
}

// ---------------------------------------------------------------------------
// K4: persistent GEMM (R8 config, unchanged): 148 x 512, W in smem,
// A 128x128 tiles double-buffered via cp.async, 2r x 16c per thread.
// ---------------------------------------------------------------------------
__global__ void __launch_bounds__(512, 1) gemm_xout_w(
    const float* __restrict__ x_out,
    const float* __restrict__ W,
    int n)
{
    extern __shared__ float smem[];
    float* Ws = smem;
    float* As = smem + D * D;

    const int tid    = threadIdx.x;
    const int bid    = blockIdx.x;
    const int ntiles = (n + GBM - 1) / GBM;

    #pragma unroll
    for (int i = tid; i < (D * D) / 4; i += 512)
        ((float4*)Ws)[i] = ((const float4*)W)[i];

    uint32_t as_base;
    asm("{ .reg .u64 t; cvta.to.shared.u64 t, %1; cvt.u32.u64 %0, t; }"
        : "=r"(as_base) : "l"(As));

    const int kS = tid & 127;
    const int rS = tid >> 7;

    if (bid < ntiles) {
        #pragma unroll
        for (int p = 0; p < 32; p++) {
            int rr = p * 4 + rS;
            int grow = bid * GBM + rr;
            if (grow >= n) grow = n - 1;
            cp_async4(as_base + (uint32_t)(kS * AST + rr) * 4,
                      &x_out[(size_t)grow * D + kS]);
        }
        asm volatile("cp.async.commit_group;");
    }

    const int r0 = tid & 63;
    const int cg = tid >> 6;

    int buf = 0;
    for (int t = bid; t < ntiles; t += NSM) {
        bool has_next = (t + NSM) < ntiles;
        if (has_next) {
            int tn = t + NSM;
            uint32_t dstb = as_base + (uint32_t)((buf ^ 1) * ASZ) * 4;
            #pragma unroll
            for (int p = 0; p < 32; p++) {
                int rr = p * 4 + rS;
                int grow = tn * GBM + rr;
                if (grow >= n) grow = n - 1;
                cp_async4(dstb + (uint32_t)(kS * AST + rr) * 4,
                          &x_out[(size_t)grow * D + kS]);
            }
            asm volatile("cp.async.commit_group;");
            asm volatile("cp.async.wait_group 1;");
        } else {
            asm volatile("cp.async.wait_group 0;");
        }
        __syncthreads();

        const float* A = As + buf * ASZ;
        unsigned long long acc[16];
        #pragma unroll
        for (int j = 0; j < 16; j++) acc[j] = 0ull;

        #pragma unroll 8
        for (int kk = 0; kk < D; kk++) {
            float a0 = A[kk * AST + r0];
            float a1 = A[kk * AST + r0 + 64];
            unsigned long long aa0, aa1;
            asm("mov.b64 %0, {%1, %1};" : "=l"(aa0) : "r"(__float_as_uint(a0)));
            asm("mov.b64 %0, {%1, %1};" : "=l"(aa1) : "r"(__float_as_uint(a1)));
            const ulonglong2* wp = reinterpret_cast<const ulonglong2*>(&Ws[kk * D + cg * 16]);
            ulonglong2 u0 = wp[0];
            ulonglong2 u1 = wp[1];
            ulonglong2 u2 = wp[2];
            ulonglong2 u3 = wp[3];
            asm("fma.rn.f32x2 %0, %1, %2, %0;" : "+l"(acc[0])  : "l"(aa0), "l"(u0.x));
            asm("fma.rn.f32x2 %0, %1, %2, %0;" : "+l"(acc[1])  : "l"(aa0), "l"(u0.y));
            asm("fma.rn.f32x2 %0, %1, %2, %0;" : "+l"(acc[2])  : "l"(aa0), "l"(u1.x));
            asm("fma.rn.f32x2 %0, %1, %2, %0;" : "+l"(acc[3])  : "l"(aa0), "l"(u1.y));
            asm("fma.rn.f32x2 %0, %1, %2, %0;" : "+l"(acc[4])  : "l"(aa0), "l"(u2.x));
            asm("fma.rn.f32x2 %0, %1, %2, %0;" : "+l"(acc[5])  : "l"(aa0), "l"(u2.y));
            asm("fma.rn.f32x2 %0, %1, %2, %0;" : "+l"(acc[6])  : "l"(aa0), "l"(u3.x));
            asm("fma.rn.f32x2 %0, %1, %2, %0;" : "+l"(acc[7])  : "l"(aa0), "l"(u3.y));
            asm("fma.rn.f32x2 %0, %1, %2, %0;" : "+l"(acc[8])  : "l"(aa1), "l"(u0.x));
            asm("fma.rn.f32x2 %0, %1, %2, %0;" : "+l"(acc[9])  : "l"(aa1), "l"(u0.y));
            asm("fma.rn.f32x2 %0, %1, %2, %0;" : "+l"(acc[10]) : "l"(aa1), "l"(u1.x));
            asm("fma.rn.f32x2 %0, %1, %2, %0;" : "+l"(acc[11]) : "l"(aa1), "l"(u1.y));
            asm("fma.rn.f32x2 %0, %1, %2, %0;" : "+l"(acc[12]) : "l"(aa1), "l"(u2.x));
            asm("fma.rn.f32x2 %0, %1, %2, %0;" : "+l"(acc[13]) : "l"(aa1), "l"(u2.y));
            asm("fma.rn.f32x2 %0, %1, %2, %0;" : "+l"(acc[14]) : "l"(aa1), "l"(u3.x));
            asm("fma.rn.f32x2 %0, %1, %2, %0;" : "+l"(acc[15]) : "l"(aa1), "l"(u3.y));
        }

        int gr0 = t * GBM + r0;
        int gr1 = gr0 + 64;
        if (gr0 < n) {
            float* dst = g_y + (size_t)gr0 * D + cg * 16;
            stg_el32B(dst,     acc[0], acc[1], acc[2],  acc[3]);
            stg_el32B(dst + 8, acc[4], acc[5], acc[6],  acc[7]);
        }
        if (gr1 < n) {
            float* dst = g_y + (size_t)gr1 * D + cg * 16;
            stg_el32B(dst,     acc[8],  acc[9],  acc[10], acc[11]);
            stg_el32B(dst + 8, acc[12], acc[13], acc[14], acc[15]);
        }

        __syncthreads();
        buf ^= 1;
    }
}

// ---------------------------------------------------------------------------
// K5: persistent bucketed edge kernel. CTA owns a contiguous BUCKET range
// (contiguous src rows) -> same-src edges processed on the same SM: y rows
// hit L1 after first touch. x_in stays L2-pinned via evict_last.
// ---------------------------------------------------------------------------
__global__ void __launch_bounds__(1024, 1) edge_bucketed(
    const float* __restrict__ x_in,
    float* __restrict__ out,
    int nb)
{
    const int bid  = blockIdx.x;
    const int tid  = threadIdx.x;
    const int wE   = tid >> 5;           // 0..31
    const int lane = tid & 31;
    const int half = lane >> 4;
    const int sub  = lane & 15;

    int b_lo = (int)((long long)bid * nb / NSM);
    int b_hi = (int)((long long)(bid + 1) * nb / NSM);
    int eBeg = g_start[b_lo];
    int eEnd = g_start[b_hi];

    for (int e = eBeg + wE * 2 + half; e < eEnd; e += 64) {
        int4 t = __ldcs(&g_sorted[e]);   // (src, dst, eid)

        float4 a0, a1, b0, b1;
        ldg_el32B(g_y  + (size_t)t.x * D + sub * 8, a0, a1);
        ldg_el32B(x_in + (size_t)t.y * D + sub * 8, b0, b1);

        float v = a0.x * b0.x + a0.y * b0.y + a0.z * b0.z + a0.w * b0.w
                + a1.x * b1.x + a1.y * b1.y + a1.z * b1.z + a1.w * b1.w;

        #pragma unroll
        for (int o = 8; o > 0; o >>= 1)
            v += __shfl_xor_sync(0xFFFFFFFFu, v, o);

        if (sub == 0)
            __stcs(&out[t.z], 1.0f / (1.0f + __expf(-v)));
    }
}

// ---------------------------------------------------------------------------
// fallback flat edge kernel (if sizes exceed static buffers)
// ---------------------------------------------------------------------------
__global__ void __launch_bounds__(256) edge_bilinear(
    const float* __restrict__ x_in,
    const void* __restrict__ ei,
    float* __restrict__ out,
    int E)
{
    const unsigned int gthread = blockIdx.x * blockDim.x + threadIdx.x;
    const int warp_id = (int)(gthread >> 5);
    const int lane = threadIdx.x & 31;
    const int half = lane >> 4;
    const int sub  = lane & 15;
    const int e    = warp_id * 2 + half;
    if (e >= E) return;

    long long s, d;
    if (g_bad) {
        const int* p = (const int*)ei;
        s = __ldcs(&p[e]); d = __ldcs(&p[E + e]);
    } else {
        const long long* p = (const long long*)ei;
        s = __ldcs(&p[e]); d = __ldcs(&p[(long long)E + e]);
    }
    float4 a0, a1, b0, b1;
    ldg_el32B(g_y  + s * D + sub * 8, a0, a1);
    ldg_el32B(x_in + d * D + sub * 8, b0, b1);
    float v = a0.x * b0.x + a0.y * b0.y + a0.z * b0.z + a0.w * b0.w
            + a1.x * b1.x + a1.y * b1.y + a1.z * b1.z + a1.w * b1.w;
    #pragma unroll
    for (int o = 8; o > 0; o >>= 1)
        v += __shfl_xor_sync(0xFFFFFFFFu, v, o);
    if (sub == 0)
        __stcs(&out[e], 1.0f / (1.0f + __expf(-v)));
}

// ---------------------------------------------------------------------------
#define GEMM_SMEM ((D * D + 2 * ASZ) * sizeof(float))

extern "C" void kernel_launch(void* const* d_in, const int* in_sizes, int n_in,
                              void* d_out, int out_size)
{
    int i_xin = 0, i_xout = 1, i_ei = 2, i_w = 3;

    if (n_in == 4) {
        int w_idx = -1, ei_idx = -1;
        for (int i = 0; i < 4; i++)
            if (in_sizes[i] == D * D) w_idx = i;
        int idx[3], c = 0;
        for (int i = 0; i < 4; i++) if (i != w_idx) idx[c++] = i;
        if (w_idx >= 0 && c == 3) {
            if (in_sizes[idx[0]] == in_sizes[idx[1]])      { i_xin = idx[0]; i_xout = idx[1]; ei_idx = idx[2]; }
            else if (in_sizes[idx[0]] == in_sizes[idx[2]]) { i_xin = idx[0]; i_xout = idx[2]; ei_idx = idx[1]; }
            else                                            { i_xin = idx[1]; i_xout = idx[2]; ei_idx = idx[0]; }
            i_w = w_idx; i_ei = ei_idx;
        }
    }

    const float* x_in  = (const float*)d_in[i_xin];
    const float* x_out = (const float*)d_in[i_xout];
    const void*  ei    = d_in[i_ei];
    const float* W     = (const float*)d_in[i_w];
    float*       out   = (float*)d_out;

    int n = in_sizes[i_xin] / D;
    if (n > MAX_NODES) n = MAX_NODES;
    int E = in_sizes[i_ei] / 2;
    int nb = ((n + (1 << BSHIFT) - 1) >> BSHIFT);

    static int smem_set = 0;
    if (!smem_set) {
        cudaFuncSetAttribute(gemm_xout_w, cudaFuncAttributeMaxDynamicSharedMemorySize,
                             (int)GEMM_SMEM);
        smem_set = 1;
    }

    bool bucketable = (E <= MAX_EDGES) && (nb + 1 <= MAX_NB);

    init_k<<<64, 256>>>((const unsigned int*)ei, in_sizes[i_ei] * 2, nb);
    if (bucketable) {
        hist_k<<<1024, 256>>>(ei, E);
        scan_k<<<1, 1024>>>(nb, E);
        scatter_k<<<1024, 256>>>(ei, E);
    }

    gemm_xout_w<<<NSM, 512, GEMM_SMEM>>>(x_out, W, n);

    if (bucketable) {
        edge_bucketed<<<NSM, 1024>>>(x_in, out, nb);
    } else {
        long long total_threads = ((long long)E + 1) / 2 * 32;
        int blocks = (int)((total_threads + 255) / 256);
        edge_bilinear<<<blocks, 256>>>(x_in, ei, out, E);
    }
}

// round 13
// speedup vs baseline: 2.1826x; 2.1826x over previous
#include <cuda_runtime.h>
#include <stdint.h>

#define D 128
#define MAX_NODES 100000
#define NSM 148
#define GBM 128
#define AST 129
#define ASZ (D * AST)

// 51.2 MB scratch for y = x_out @ W0
__device__ float g_y[MAX_NODES * D];

// ---------------------------------------------------------------------------
// helpers
// ---------------------------------------------------------------------------
__device__ __forceinline__ void ldg_el32B(const float* p, float4& lo, float4& hi) {
    unsigned long long x0, x1, x2, x3;
    asm volatile("ld.global.nc.L2::evict_last.v4.b64 {%0,%1,%2,%3}, [%4];"
                 : "=l"(x0), "=l"(x1), "=l"(x2), "=l"(x3) : "l"(p));
    lo.x = __uint_as_float((unsigned)x0); lo.y = __uint_as_float((unsigned)(x0 >> 32));
    lo.z = __uint_as_float((unsigned)x1); lo.w = __uint_as_float((unsigned)(x1 >> 32));
    hi.x = __uint_as_float((unsigned)x2); hi.y = __uint_as_float((unsigned)(x2 >> 32));
    hi.z = __uint_as_float((unsigned)x3); hi.w = __uint_as_float((unsigned)(x3 >> 32));
}
__device__ __forceinline__ void stg_el32B(float* p, unsigned long long x0,
                                          unsigned long long x1,
                                          unsigned long long x2,
                                          unsigned long long x3) {
    asm volatile("st.global.L2::evict_last.v4.b64 [%0], {%1,%2,%3,%4};"
                 :: "l"(p), "l"(x0), "l"(x1), "l"(x2), "l"(x3) : "memory");
}
__device__ __forceinline__ void cp_async4(uint32_t smem_addr, const float* gptr) {
    asm volatile("cp.async.ca.shared.global [%0], [%1], 4;"
                 :: "r"(smem_addr), "l"(gptr));
}

// ---------------------------------------------------------------------------
// Persistent GEMM (R8 + explicit kk software pipelining):
// 148 CTAs x 512 thr, W resident in smem, A 128x128 tiles double-buffered
// via cp.async; thread = 2 rows x 16 cols (16 packed f32x2 accumulators).
// Inner loop prefetches next-kk A scalars + W 64B slice into registers.
// ---------------------------------------------------------------------------
__global__ void __launch_bounds__(512, 1) gemm_xout_w(
    const float* __restrict__ x_out,
    const float* __restrict__ W,
    int n)
{
    extern __shared__ float smem[];
    float* Ws = smem;              // [k*128 + c], 64 KB
    float* As = smem + D * D;      // 2 buffers [k*129 + r]

    const int tid    = threadIdx.x;
    const int bid    = blockIdx.x;
    const int ntiles = (n + GBM - 1) / GBM;

    #pragma unroll
    for (int i = tid; i < (D * D) / 4; i += 512)
        ((float4*)Ws)[i] = ((const float4*)W)[i];

    uint32_t as_base;
    asm("{ .reg .u64 t; cvta.to.shared.u64 t, %1; cvt.u32.u64 %0, t; }"
        : "=r"(as_base) : "l"(As));

    const int kS = tid & 127;
    const int rS = tid >> 7;

    if (bid < ntiles) {
        #pragma unroll
        for (int p = 0; p < 32; p++) {
            int rr = p * 4 + rS;
            int grow = bid * GBM + rr;
            if (grow >= n) grow = n - 1;
            cp_async4(as_base + (uint32_t)(kS * AST + rr) * 4,
                      &x_out[(size_t)grow * D + kS]);
        }
        asm volatile("cp.async.commit_group;");
    }

    const int r0 = tid & 63;
    const int cg = tid >> 6;

    int buf = 0;
    for (int t = bid; t < ntiles; t += NSM) {
        bool has_next = (t + NSM) < ntiles;
        if (has_next) {
            int tn = t + NSM;
            uint32_t dstb = as_base + (uint32_t)((buf ^ 1) * ASZ) * 4;
            #pragma unroll
            for (int p = 0; p < 32; p++) {
                int rr = p * 4 + rS;
                int grow = tn * GBM + rr;
                if (grow >= n) grow = n - 1;
                cp_async4(dstb + (uint32_t)(kS * AST + rr) * 4,
                          &x_out[(size_t)grow * D + kS]);
            }
            asm volatile("cp.async.commit_group;");
            asm volatile("cp.async.wait_group 1;");
        } else {
            asm volatile("cp.async.wait_group 0;");
        }
        __syncthreads();

        const float* A = As + buf * ASZ;
        const ulonglong2* Wp = reinterpret_cast<const ulonglong2*>(&Ws[cg * 16]);
        unsigned long long acc[16];
        #pragma unroll
        for (int j = 0; j < 16; j++) acc[j] = 0ull;

        // --- software-pipelined over kk: prefetch kk+1 operands first ---
        float a0 = A[r0];
        float a1 = A[r0 + 64];
        ulonglong2 u0 = Wp[0];
        ulonglong2 u1 = Wp[1];
        ulonglong2 u2 = Wp[2];
        ulonglong2 u3 = Wp[3];

        #pragma unroll 8
        for (int kk = 0; kk < D; kk++) {
            float na0, na1;
            ulonglong2 n0, n1, n2, n3;
            if (kk < D - 1) {
                na0 = A[(kk + 1) * AST + r0];
                na1 = A[(kk + 1) * AST + r0 + 64];
                const ulonglong2* wn = reinterpret_cast<const ulonglong2*>(
                    (const char*)Wp + (size_t)(kk + 1) * D * 4);
                n0 = wn[0]; n1 = wn[1]; n2 = wn[2]; n3 = wn[3];
            }
            unsigned long long aa0, aa1;
            asm("mov.b64 %0, {%1, %1};" : "=l"(aa0) : "r"(__float_as_uint(a0)));
            asm("mov.b64 %0, {%1, %1};" : "=l"(aa1) : "r"(__float_as_uint(a1)));
            asm("fma.rn.f32x2 %0, %1, %2, %0;" : "+l"(acc[0])  : "l"(aa0), "l"(u0.x));
            asm("fma.rn.f32x2 %0, %1, %2, %0;" : "+l"(acc[1])  : "l"(aa0), "l"(u0.y));
            asm("fma.rn.f32x2 %0, %1, %2, %0;" : "+l"(acc[2])  : "l"(aa0), "l"(u1.x));
            asm("fma.rn.f32x2 %0, %1, %2, %0;" : "+l"(acc[3])  : "l"(aa0), "l"(u1.y));
            asm("fma.rn.f32x2 %0, %1, %2, %0;" : "+l"(acc[4])  : "l"(aa0), "l"(u2.x));
            asm("fma.rn.f32x2 %0, %1, %2, %0;" : "+l"(acc[5])  : "l"(aa0), "l"(u2.y));
            asm("fma.rn.f32x2 %0, %1, %2, %0;" : "+l"(acc[6])  : "l"(aa0), "l"(u3.x));
            asm("fma.rn.f32x2 %0, %1, %2, %0;" : "+l"(acc[7])  : "l"(aa0), "l"(u3.y));
            asm("fma.rn.f32x2 %0, %1, %2, %0;" : "+l"(acc[8])  : "l"(aa1), "l"(u0.x));
            asm("fma.rn.f32x2 %0, %1, %2, %0;" : "+l"(acc[9])  : "l"(aa1), "l"(u0.y));
            asm("fma.rn.f32x2 %0, %1, %2, %0;" : "+l"(acc[10]) : "l"(aa1), "l"(u1.x));
            asm("fma.rn.f32x2 %0, %1, %2, %0;" : "+l"(acc[11]) : "l"(aa1), "l"(u1.y));
            asm("fma.rn.f32x2 %0, %1, %2, %0;" : "+l"(acc[12]) : "l"(aa1), "l"(u2.x));
            asm("fma.rn.f32x2 %0, %1, %2, %0;" : "+l"(acc[13]) : "l"(aa1), "l"(u2.y));
            asm("fma.rn.f32x2 %0, %1, %2, %0;" : "+l"(acc[14]) : "l"(aa1), "l"(u3.x));
            asm("fma.rn.f32x2 %0, %1, %2, %0;" : "+l"(acc[15]) : "l"(aa1), "l"(u3.y));
            if (kk < D - 1) {
                a0 = na0; a1 = na1;
                u0 = n0; u1 = n1; u2 = n2; u3 = n3;
            }
        }

        int gr0 = t * GBM + r0;
        int gr1 = gr0 + 64;
        if (gr0 < n) {
            float* dst = g_y + (size_t)gr0 * D + cg * 16;
            stg_el32B(dst,     acc[0], acc[1], acc[2],  acc[3]);
            stg_el32B(dst + 8, acc[4], acc[5], acc[6],  acc[7]);
        }
        if (gr1 < n) {
            float* dst = g_y + (size_t)gr1 * D + cg * 16;
            stg_el32B(dst,     acc[8],  acc[9],  acc[10], acc[11]);
            stg_el32B(dst + 8, acc[12], acc[13], acc[14], acc[15]);
        }

        __syncthreads();
        buf ^= 1;
    }
}

// ---------------------------------------------------------------------------
// Edge kernel (R8 scheme, dtype check inlined):
// out[e] = sigmoid(dot(y[src], x_in[dst])); warp = 2 edges, 16 lanes/edge,
// 32B evict-last gathers; streams evict-first; coalesced out stores.
// ---------------------------------------------------------------------------
__global__ void __launch_bounds__(256) edge_bilinear(
    const float* __restrict__ x_in,
    const void* __restrict__ ei,
    float* __restrict__ out,
    int E)
{
    // inline dtype detection: true int64 -> all high words zero in the first
    // 8 words; int32 indices -> odd words are random nonzero indices.
    const uint4 w0 = __ldg((const uint4*)ei);
    const uint4 w1 = __ldg((const uint4*)ei + 1);
    const bool is32 = ((w0.y | w0.w | w1.y | w1.w) != 0u);

    const unsigned int gthread = blockIdx.x * blockDim.x + threadIdx.x;
    const int warp_id = (int)(gthread >> 5);
    const int lane = threadIdx.x & 31;
    const int half = lane >> 4;
    const int sub  = lane & 15;
    const int e    = warp_id * 2 + half;
    if (e >= E) return;

    long long s, d;
    if (is32) {
        const int* p = (const int*)ei;
        s = __ldcs(&p[e]);
        d = __ldcs(&p[E + e]);
    } else {
        const long long* p = (const long long*)ei;
        s = __ldcs(&p[e]);
        d = __ldcs(&p[(long long)E + e]);
    }

    float4 a0, a1, b0, b1;
    ldg_el32B(g_y  + s * D + sub * 8, a0, a1);
    ldg_el32B(x_in + d * D + sub * 8, b0, b1);

    float v = a0.x * b0.x + a0.y * b0.y + a0.z * b0.z + a0.w * b0.w
            + a1.x * b1.x + a1.y * b1.y + a1.z * b1.z + a1.w * b1.w;

    #pragma unroll
    for (int o = 8; o > 0; o >>= 1)
        v += __shfl_xor_sync(0xFFFFFFFFu, v, o);

    if (sub == 0)
        __stcs(&out[e], 1.0f / (1.0f + __expf(-v)));
}

// ---------------------------------------------------------------------------
// Launch
// ---------------------------------------------------------------------------
#define GEMM_SMEM ((D * D + 2 * ASZ) * sizeof(float))

extern "C" void kernel_launch(void* const* d_in, const int* in_sizes, int n_in,
                              void* d_out, int out_size)
{
    int i_xin = 0, i_xout = 1, i_ei = 2, i_w = 3;

    if (n_in == 4) {
        int w_idx = -1, ei_idx = -1;
        for (int i = 0; i < 4; i++)
            if (in_sizes[i] == D * D) w_idx = i;
        int idx[3], c = 0;
        for (int i = 0; i < 4; i++) if (i != w_idx) idx[c++] = i;
        if (w_idx >= 0 && c == 3) {
            if (in_sizes[idx[0]] == in_sizes[idx[1]])      { i_xin = idx[0]; i_xout = idx[1]; ei_idx = idx[2]; }
            else if (in_sizes[idx[0]] == in_sizes[idx[2]]) { i_xin = idx[0]; i_xout = idx[2]; ei_idx = idx[1]; }
            else                                            { i_xin = idx[1]; i_xout = idx[2]; ei_idx = idx[0]; }
            i_w = w_idx; i_ei = ei_idx;
        }
    }

    const float* x_in  = (const float*)d_in[i_xin];
    const float* x_out = (const float*)d_in[i_xout];
    const void*  ei    = d_in[i_ei];
    const float* W     = (const float*)d_in[i_w];
    float*       out   = (float*)d_out;

    int n = in_sizes[i_xin] / D;
    if (n > MAX_NODES) n = MAX_NODES;
    int E = in_sizes[i_ei] / 2;

    static int smem_set = 0;
    if (!smem_set) {
        cudaFuncSetAttribute(gemm_xout_w, cudaFuncAttributeMaxDynamicSharedMemorySize,
                             (int)GEMM_SMEM);
        smem_set = 1;
    }

    gemm_xout_w<<<NSM, 512, GEMM_SMEM>>>(x_out, W, n);

    {
        long long total_threads = ((long long)E + 1) / 2 * 32;
        int blocks = (int)((total_threads + 255) / 256);
        edge_bilinear<<<blocks, 256>>>(x_in, ei, out, E);
    }
}

// round 14
// speedup vs baseline: 2.4694x; 1.1314x over previous
#include <cuda_runtime.h>
#include <stdint.h>

#define D 128
#define MAX_NODES 100000
#define NSM 148
#define GBM 128
#define AST 129
#define ASZ (D * AST)

// 51.2 MB scratch for y = x_out @ W0
__device__ float g_y[MAX_NODES * D];

// ---------------------------------------------------------------------------
// helpers
// ---------------------------------------------------------------------------
__device__ __forceinline__ void ldg_el32B(const float* p, float4& lo, float4& hi) {
    unsigned long long x0, x1, x2, x3;
    asm volatile("ld.global.nc.L2::evict_last.v4.b64 {%0,%1,%2,%3}, [%4];"
                 : "=l"(x0), "=l"(x1), "=l"(x2), "=l"(x3) : "l"(p));
    lo.x = __uint_as_float((unsigned)x0); lo.y = __uint_as_float((unsigned)(x0 >> 32));
    lo.z = __uint_as_float((unsigned)x1); lo.w = __uint_as_float((unsigned)(x1 >> 32));
    hi.x = __uint_as_float((unsigned)x2); hi.y = __uint_as_float((unsigned)(x2 >> 32));
    hi.z = __uint_as_float((unsigned)x3); hi.w = __uint_as_float((unsigned)(x3 >> 32));
}
__device__ __forceinline__ void stg_el32B(float* p, unsigned long long x0,
                                          unsigned long long x1,
                                          unsigned long long x2,
                                          unsigned long long x3) {
    asm volatile("st.global.L2::evict_last.v4.b64 [%0], {%1,%2,%3,%4};"
                 :: "l"(p), "l"(x0), "l"(x1), "l"(x2), "l"(x3) : "memory");
}
// cp.async with L2 evict-first policy: x_out streams without evicting the
// pinned gather tables (x_in / g_y) from L2.
__device__ __forceinline__ void cp_async4_ef(uint32_t smem_addr, const float* gptr,
                                             unsigned long long pol) {
    asm volatile("cp.async.ca.shared.global.L2::cache_hint [%0], [%1], 4, %2;"
                 :: "r"(smem_addr), "l"(gptr), "l"(pol));
}

// ---------------------------------------------------------------------------
// Persistent GEMM (exact R8 config): 148 CTAs x 512 thr, W resident in smem,
// A 128x128 tiles double-buffered via cp.async (evict-first L2 policy);
// thread = 2 rows x 16 cols as 16 packed f32x2 accumulators.
// ---------------------------------------------------------------------------
__global__ void __launch_bounds__(512, 1) gemm_xout_w(
    const float* __restrict__ x_out,
    const float* __restrict__ W,
    int n)
{
    extern __shared__ float smem[];
    float* Ws = smem;
    float* As = smem + D * D;

    const int tid    = threadIdx.x;
    const int bid    = blockIdx.x;
    const int ntiles = (n + GBM - 1) / GBM;

    #pragma unroll
    for (int i = tid; i < (D * D) / 4; i += 512)
        ((float4*)Ws)[i] = ((const float4*)W)[i];

    unsigned long long pol;
    asm("createpolicy.fractional.L2::evict_first.b64 %0, 1.0;" : "=l"(pol));

    uint32_t as_base;
    asm("{ .reg .u64 t; cvta.to.shared.u64 t, %1; cvt.u32.u64 %0, t; }"
        : "=r"(as_base) : "l"(As));

    const int kS = tid & 127;
    const int rS = tid >> 7;

    if (bid < ntiles) {
        #pragma unroll
        for (int p = 0; p < 32; p++) {
            int rr = p * 4 + rS;
            int grow = bid * GBM + rr;
            if (grow >= n) grow = n - 1;
            cp_async4_ef(as_base + (uint32_t)(kS * AST + rr) * 4,
                         &x_out[(size_t)grow * D + kS], pol);
        }
        asm volatile("cp.async.commit_group;");
    }

    const int r0 = tid & 63;
    const int cg = tid >> 6;

    int buf = 0;
    for (int t = bid; t < ntiles; t += NSM) {
        bool has_next = (t + NSM) < ntiles;
        if (has_next) {
            int tn = t + NSM;
            uint32_t dstb = as_base + (uint32_t)((buf ^ 1) * ASZ) * 4;
            #pragma unroll
            for (int p = 0; p < 32; p++) {
                int rr = p * 4 + rS;
                int grow = tn * GBM + rr;
                if (grow >= n) grow = n - 1;
                cp_async4_ef(dstb + (uint32_t)(kS * AST + rr) * 4,
                             &x_out[(size_t)grow * D + kS], pol);
            }
            asm volatile("cp.async.commit_group;");
            asm volatile("cp.async.wait_group 1;");
        } else {
            asm volatile("cp.async.wait_group 0;");
        }
        __syncthreads();

        const float* A = As + buf * ASZ;
        unsigned long long acc[16];
        #pragma unroll
        for (int j = 0; j < 16; j++) acc[j] = 0ull;

        #pragma unroll 8
        for (int kk = 0; kk < D; kk++) {
            float a0 = A[kk * AST + r0];
            float a1 = A[kk * AST + r0 + 64];
            unsigned long long aa0, aa1;
            asm("mov.b64 %0, {%1, %1};" : "=l"(aa0) : "r"(__float_as_uint(a0)));
            asm("mov.b64 %0, {%1, %1};" : "=l"(aa1) : "r"(__float_as_uint(a1)));
            const ulonglong2* wp = reinterpret_cast<const ulonglong2*>(&Ws[kk * D + cg * 16]);
            ulonglong2 u0 = wp[0];
            ulonglong2 u1 = wp[1];
            ulonglong2 u2 = wp[2];
            ulonglong2 u3 = wp[3];
            asm("fma.rn.f32x2 %0, %1, %2, %0;" : "+l"(acc[0])  : "l"(aa0), "l"(u0.x));
            asm("fma.rn.f32x2 %0, %1, %2, %0;" : "+l"(acc[1])  : "l"(aa0), "l"(u0.y));
            asm("fma.rn.f32x2 %0, %1, %2, %0;" : "+l"(acc[2])  : "l"(aa0), "l"(u1.x));
            asm("fma.rn.f32x2 %0, %1, %2, %0;" : "+l"(acc[3])  : "l"(aa0), "l"(u1.y));
            asm("fma.rn.f32x2 %0, %1, %2, %0;" : "+l"(acc[4])  : "l"(aa0), "l"(u2.x));
            asm("fma.rn.f32x2 %0, %1, %2, %0;" : "+l"(acc[5])  : "l"(aa0), "l"(u2.y));
            asm("fma.rn.f32x2 %0, %1, %2, %0;" : "+l"(acc[6])  : "l"(aa0), "l"(u3.x));
            asm("fma.rn.f32x2 %0, %1, %2, %0;" : "+l"(acc[7])  : "l"(aa0), "l"(u3.y));
            asm("fma.rn.f32x2 %0, %1, %2, %0;" : "+l"(acc[8])  : "l"(aa1), "l"(u0.x));
            asm("fma.rn.f32x2 %0, %1, %2, %0;" : "+l"(acc[9])  : "l"(aa1), "l"(u0.y));
            asm("fma.rn.f32x2 %0, %1, %2, %0;" : "+l"(acc[10]) : "l"(aa1), "l"(u1.x));
            asm("fma.rn.f32x2 %0, %1, %2, %0;" : "+l"(acc[11]) : "l"(aa1), "l"(u1.y));
            asm("fma.rn.f32x2 %0, %1, %2, %0;" : "+l"(acc[12]) : "l"(aa1), "l"(u2.x));
            asm("fma.rn.f32x2 %0, %1, %2, %0;" : "+l"(acc[13]) : "l"(aa1), "l"(u2.y));
            asm("fma.rn.f32x2 %0, %1, %2, %0;" : "+l"(acc[14]) : "l"(aa1), "l"(u3.x));
            asm("fma.rn.f32x2 %0, %1, %2, %0;" : "+l"(acc[15]) : "l"(aa1), "l"(u3.y));
        }

        int gr0 = t * GBM + r0;
        int gr1 = gr0 + 64;
        if (gr0 < n) {
            float* dst = g_y + (size_t)gr0 * D + cg * 16;
            stg_el32B(dst,     acc[0], acc[1], acc[2],  acc[3]);
            stg_el32B(dst + 8, acc[4], acc[5], acc[6],  acc[7]);
        }
        if (gr1 < n) {
            float* dst = g_y + (size_t)gr1 * D + cg * 16;
            stg_el32B(dst,     acc[8],  acc[9],  acc[10], acc[11]);
            stg_el32B(dst + 8, acc[12], acc[13], acc[14], acc[15]);
        }

        __syncthreads();
        buf ^= 1;
    }
}

// ---------------------------------------------------------------------------
// Edge kernel: one warp = 4 edges; each 16-lane group handles 2 edges with
// all 4 gathers (2x y, 2x x_in) issued before any use -> MLP 4/thread.
// Inline dtype detection; evict-last on gathers; evict-first streams.
// ---------------------------------------------------------------------------
__global__ void __launch_bounds__(256) edge_bilinear(
    const float* __restrict__ x_in,
    const void* __restrict__ ei,
    float* __restrict__ out,
    int E)
{
    // dtype: true int64 -> high words zero; int32 -> odd words are indices
    const uint4 w0 = __ldg((const uint4*)ei);
    const uint4 w1 = __ldg((const uint4*)ei + 1);
    const bool is32 = ((w0.y | w0.w | w1.y | w1.w) != 0u);

    const unsigned int gthread = blockIdx.x * blockDim.x + threadIdx.x;
    const int warp_id = (int)(gthread >> 5);
    const int lane = threadIdx.x & 31;
    const int half = lane >> 4;
    const int sub  = lane & 15;
    const int e0   = warp_id * 4 + half * 2;
    const int e1   = e0 + 1;
    if (e0 >= E) return;
    const bool has1 = (e1 < E);

    long long s0, d0, s1 = 0, d1 = 0;
    if (is32) {
        const int* p = (const int*)ei;
        s0 = __ldcs(&p[e0]);  d0 = __ldcs(&p[E + e0]);
        if (has1) { s1 = __ldcs(&p[e1]); d1 = __ldcs(&p[E + e1]); }
    } else {
        const long long* p = (const long long*)ei;
        s0 = __ldcs(&p[e0]);  d0 = __ldcs(&p[(long long)E + e0]);
        if (has1) { s1 = __ldcs(&p[e1]); d1 = __ldcs(&p[(long long)E + e1]); }
    }

    // issue all gathers before any use (4x 32B in flight per thread)
    float4 A0a, A0b, B0a, B0b, A1a, A1b, B1a, B1b;
    ldg_el32B(g_y  + s0 * D + sub * 8, A0a, A0b);
    ldg_el32B(x_in + d0 * D + sub * 8, B0a, B0b);
    if (has1) {
        ldg_el32B(g_y  + s1 * D + sub * 8, A1a, A1b);
        ldg_el32B(x_in + d1 * D + sub * 8, B1a, B1b);
    }

    float v0 = A0a.x * B0a.x + A0a.y * B0a.y + A0a.z * B0a.z + A0a.w * B0a.w
             + A0b.x * B0b.x + A0b.y * B0b.y + A0b.z * B0b.z + A0b.w * B0b.w;
    float v1 = 0.0f;
    if (has1)
        v1 = A1a.x * B1a.x + A1a.y * B1a.y + A1a.z * B1a.z + A1a.w * B1a.w
           + A1b.x * B1b.x + A1b.y * B1b.y + A1b.z * B1b.z + A1b.w * B1b.w;

    #pragma unroll
    for (int o = 8; o > 0; o >>= 1) {
        v0 += __shfl_xor_sync(0xFFFFFFFFu, v0, o);
        v1 += __shfl_xor_sync(0xFFFFFFFFu, v1, o);
    }

    if (sub == 0) {
        __stcs(&out[e0], 1.0f / (1.0f + __expf(-v0)));
        if (has1)
            __stcs(&out[e1], 1.0f / (1.0f + __expf(-v1)));
    }
}

// ---------------------------------------------------------------------------
// Launch
// ---------------------------------------------------------------------------
#define GEMM_SMEM ((D * D + 2 * ASZ) * sizeof(float))

extern "C" void kernel_launch(void* const* d_in, const int* in_sizes, int n_in,
                              void* d_out, int out_size)
{
    int i_xin = 0, i_xout = 1, i_ei = 2, i_w = 3;

    if (n_in == 4) {
        int w_idx = -1, ei_idx = -1;
        for (int i = 0; i < 4; i++)
            if (in_sizes[i] == D * D) w_idx = i;
        int idx[3], c = 0;
        for (int i = 0; i < 4; i++) if (i != w_idx) idx[c++] = i;
        if (w_idx >= 0 && c == 3) {
            if (in_sizes[idx[0]] == in_sizes[idx[1]])      { i_xin = idx[0]; i_xout = idx[1]; ei_idx = idx[2]; }
            else if (in_sizes[idx[0]] == in_sizes[idx[2]]) { i_xin = idx[0]; i_xout = idx[2]; ei_idx = idx[1]; }
            else                                            { i_xin = idx[1]; i_xout = idx[2]; ei_idx = idx[0]; }
            i_w = w_idx; i_ei = ei_idx;
        }
    }

    const float* x_in  = (const float*)d_in[i_xin];
    const float* x_out = (const float*)d_in[i_xout];
    const void*  ei    = d_in[i_ei];
    const float* W     = (const float*)d_in[i_w];
    float*       out   = (float*)d_out;

    int n = in_sizes[i_xin] / D;
    if (n > MAX_NODES) n = MAX_NODES;
    int E = in_sizes[i_ei] / 2;

    static int smem_set = 0;
    if (!smem_set) {
        cudaFuncSetAttribute(gemm_xout_w, cudaFuncAttributeMaxDynamicSharedMemorySize,
                             (int)GEMM_SMEM);
        smem_set = 1;
    }

    gemm_xout_w<<<NSM, 512, GEMM_SMEM>>>(x_out, W, n);

    {
        // one warp per 4 edges
        long long warps = ((long long)E + 3) / 4;
        long long total_threads = warps * 32;
        int blocks = (int)((total_threads + 255) / 256);
        edge_bilinear<<<blocks, 256>>>(x_in, ei, out, E);
    }
}

// round 15
// speedup vs baseline: 2.5045x; 1.0142x over previous
#include <cuda_runtime.h>
#include <stdint.h>

#define D 128
#define MAX_NODES 100000
#define NSM 148
#define GBM 128
#define AST 129
#define ASZ (D * AST)

// 51.2 MB scratch for y = x_out @ W0
__device__ float g_y[MAX_NODES * D];

// ---------------------------------------------------------------------------
// helpers
// ---------------------------------------------------------------------------
__device__ __forceinline__ void ldg_el32B(const float* p, float4& lo, float4& hi) {
    unsigned long long x0, x1, x2, x3;
    asm volatile("ld.global.nc.L2::evict_last.v4.b64 {%0,%1,%2,%3}, [%4];"
                 : "=l"(x0), "=l"(x1), "=l"(x2), "=l"(x3) : "l"(p));
    lo.x = __uint_as_float((unsigned)x0); lo.y = __uint_as_float((unsigned)(x0 >> 32));
    lo.z = __uint_as_float((unsigned)x1); lo.w = __uint_as_float((unsigned)(x1 >> 32));
    hi.x = __uint_as_float((unsigned)x2); hi.y = __uint_as_float((unsigned)(x2 >> 32));
    hi.z = __uint_as_float((unsigned)x3); hi.w = __uint_as_float((unsigned)(x3 >> 32));
}
__device__ __forceinline__ void stg_el32B(float* p, unsigned long long x0,
                                          unsigned long long x1,
                                          unsigned long long x2,
                                          unsigned long long x3) {
    asm volatile("st.global.L2::evict_last.v4.b64 [%0], {%1,%2,%3,%4};"
                 :: "l"(p), "l"(x0), "l"(x1), "l"(x2), "l"(x3) : "memory");
}
__device__ __forceinline__ void cp_async4_ef(uint32_t smem_addr, const float* gptr,
                                             unsigned long long pol) {
    asm volatile("cp.async.ca.shared.global.L2::cache_hint [%0], [%1], 4, %2;"
                 :: "r"(smem_addr), "l"(gptr), "l"(pol));
}

// ---------------------------------------------------------------------------
// Persistent GEMM: 148 CTAs x 512 thr, W in smem, A 128x128 double-buffered.
// Thread = 4 rows x 8 cols (16 packed f32x2 accs). Per-kk operand footprint:
// 4 A floats + 8 W regs -> deep ptxas software pipelining of the LDS chain.
// ---------------------------------------------------------------------------
__global__ void __launch_bounds__(512, 1) gemm_xout_w(
    const float* __restrict__ x_out,
    const float* __restrict__ W,
    int n)
{
    extern __shared__ float smem[];
    float* Ws = smem;              // [k*128 + c], 64 KB
    float* As = smem + D * D;      // 2 buffers [k*129 + r]

    const int tid    = threadIdx.x;
    const int bid    = blockIdx.x;
    const int ntiles = (n + GBM - 1) / GBM;

    #pragma unroll
    for (int i = tid; i < (D * D) / 4; i += 512)
        ((float4*)Ws)[i] = ((const float4*)W)[i];

    unsigned long long pol;
    asm("createpolicy.fractional.L2::evict_first.b64 %0, 1.0;" : "=l"(pol));

    uint32_t as_base;
    asm("{ .reg .u64 t; cvta.to.shared.u64 t, %1; cvt.u32.u64 %0, t; }"
        : "=r"(as_base) : "l"(As));

    const int kS = tid & 127;
    const int rS = tid >> 7;

    if (bid < ntiles) {
        #pragma unroll
        for (int p = 0; p < 32; p++) {
            int rr = p * 4 + rS;
            int grow = bid * GBM + rr;
            if (grow >= n) grow = n - 1;
            cp_async4_ef(as_base + (uint32_t)(kS * AST + rr) * 4,
                         &x_out[(size_t)grow * D + kS], pol);
        }
        asm volatile("cp.async.commit_group;");
    }

    const int lane = tid & 31;            // rows lane, lane+32, lane+64, lane+96
    const int wcg  = tid >> 5;            // 0..15 -> cols wcg*8 .. +7

    int buf = 0;
    for (int t = bid; t < ntiles; t += NSM) {
        bool has_next = (t + NSM) < ntiles;
        if (has_next) {
            int tn = t + NSM;
            uint32_t dstb = as_base + (uint32_t)((buf ^ 1) * ASZ) * 4;
            #pragma unroll
            for (int p = 0; p < 32; p++) {
                int rr = p * 4 + rS;
                int grow = tn * GBM + rr;
                if (grow >= n) grow = n - 1;
                cp_async4_ef(dstb + (uint32_t)(kS * AST + rr) * 4,
                             &x_out[(size_t)grow * D + kS], pol);
            }
            asm volatile("cp.async.commit_group;");
            asm volatile("cp.async.wait_group 1;");
        } else {
            asm volatile("cp.async.wait_group 0;");
        }
        __syncthreads();

        const float* A = As + buf * ASZ;
        unsigned long long acc[16];
        #pragma unroll
        for (int j = 0; j < 16; j++) acc[j] = 0ull;

        #pragma unroll 8
        for (int kk = 0; kk < D; kk++) {
            float a0 = A[kk * AST + lane];
            float a1 = A[kk * AST + lane + 32];
            float a2 = A[kk * AST + lane + 64];
            float a3 = A[kk * AST + lane + 96];
            unsigned long long aa0, aa1, aa2, aa3;
            asm("mov.b64 %0, {%1, %1};" : "=l"(aa0) : "r"(__float_as_uint(a0)));
            asm("mov.b64 %0, {%1, %1};" : "=l"(aa1) : "r"(__float_as_uint(a1)));
            asm("mov.b64 %0, {%1, %1};" : "=l"(aa2) : "r"(__float_as_uint(a2)));
            asm("mov.b64 %0, {%1, %1};" : "=l"(aa3) : "r"(__float_as_uint(a3)));
            const ulonglong2* wp = reinterpret_cast<const ulonglong2*>(&Ws[kk * D + wcg * 8]);
            ulonglong2 u0 = wp[0];   // cols +0..3
            ulonglong2 u1 = wp[1];   // cols +4..7
            asm("fma.rn.f32x2 %0, %1, %2, %0;" : "+l"(acc[0])  : "l"(aa0), "l"(u0.x));
            asm("fma.rn.f32x2 %0, %1, %2, %0;" : "+l"(acc[1])  : "l"(aa0), "l"(u0.y));
            asm("fma.rn.f32x2 %0, %1, %2, %0;" : "+l"(acc[2])  : "l"(aa0), "l"(u1.x));
            asm("fma.rn.f32x2 %0, %1, %2, %0;" : "+l"(acc[3])  : "l"(aa0), "l"(u1.y));
            asm("fma.rn.f32x2 %0, %1, %2, %0;" : "+l"(acc[4])  : "l"(aa1), "l"(u0.x));
            asm("fma.rn.f32x2 %0, %1, %2, %0;" : "+l"(acc[5])  : "l"(aa1), "l"(u0.y));
            asm("fma.rn.f32x2 %0, %1, %2, %0;" : "+l"(acc[6])  : "l"(aa1), "l"(u1.x));
            asm("fma.rn.f32x2 %0, %1, %2, %0;" : "+l"(acc[7])  : "l"(aa1), "l"(u1.y));
            asm("fma.rn.f32x2 %0, %1, %2, %0;" : "+l"(acc[8])  : "l"(aa2), "l"(u0.x));
            asm("fma.rn.f32x2 %0, %1, %2, %0;" : "+l"(acc[9])  : "l"(aa2), "l"(u0.y));
            asm("fma.rn.f32x2 %0, %1, %2, %0;" : "+l"(acc[10]) : "l"(aa2), "l"(u1.x));
            asm("fma.rn.f32x2 %0, %1, %2, %0;" : "+l"(acc[11]) : "l"(aa2), "l"(u1.y));
            asm("fma.rn.f32x2 %0, %1, %2, %0;" : "+l"(acc[12]) : "l"(aa3), "l"(u0.x));
            asm("fma.rn.f32x2 %0, %1, %2, %0;" : "+l"(acc[13]) : "l"(aa3), "l"(u0.y));
            asm("fma.rn.f32x2 %0, %1, %2, %0;" : "+l"(acc[14]) : "l"(aa3), "l"(u1.x));
            asm("fma.rn.f32x2 %0, %1, %2, %0;" : "+l"(acc[15]) : "l"(aa3), "l"(u1.y));
        }

        #pragma unroll
        for (int q = 0; q < 4; q++) {
            int gr = t * GBM + lane + q * 32;
            if (gr < n) {
                float* dst = g_y + (size_t)gr * D + wcg * 8;
                stg_el32B(dst, acc[q * 4 + 0], acc[q * 4 + 1],
                               acc[q * 4 + 2], acc[q * 4 + 3]);
            }
        }

        __syncthreads();
        buf ^= 1;
    }
}

// ---------------------------------------------------------------------------
// Edge kernel (exact R14): warp = 4 edges; each 16-lane group handles 2 edges
// with all 4 gathers in flight; inline dtype detection; evict-last gathers.
// ---------------------------------------------------------------------------
__global__ void __launch_bounds__(256) edge_bilinear(
    const float* __restrict__ x_in,
    const void* __restrict__ ei,
    float* __restrict__ out,
    int E)
{
    const uint4 w0 = __ldg((const uint4*)ei);
    const uint4 w1 = __ldg((const uint4*)ei + 1);
    const bool is32 = ((w0.y | w0.w | w1.y | w1.w) != 0u);

    const unsigned int gthread = blockIdx.x * blockDim.x + threadIdx.x;
    const int warp_id = (int)(gthread >> 5);
    const int lane = threadIdx.x & 31;
    const int half = lane >> 4;
    const int sub  = lane & 15;
    const int e0   = warp_id * 4 + half * 2;
    const int e1   = e0 + 1;
    if (e0 >= E) return;
    const bool has1 = (e1 < E);

    long long s0, d0, s1 = 0, d1 = 0;
    if (is32) {
        const int* p = (const int*)ei;
        s0 = __ldcs(&p[e0]);  d0 = __ldcs(&p[E + e0]);
        if (has1) { s1 = __ldcs(&p[e1]); d1 = __ldcs(&p[E + e1]); }
    } else {
        const long long* p = (const long long*)ei;
        s0 = __ldcs(&p[e0]);  d0 = __ldcs(&p[(long long)E + e0]);
        if (has1) { s1 = __ldcs(&p[e1]); d1 = __ldcs(&p[(long long)E + e1]); }
    }

    float4 A0a, A0b, B0a, B0b, A1a, A1b, B1a, B1b;
    ldg_el32B(g_y  + s0 * D + sub * 8, A0a, A0b);
    ldg_el32B(x_in + d0 * D + sub * 8, B0a, B0b);
    if (has1) {
        ldg_el32B(g_y  + s1 * D + sub * 8, A1a, A1b);
        ldg_el32B(x_in + d1 * D + sub * 8, B1a, B1b);
    }

    float v0 = A0a.x * B0a.x + A0a.y * B0a.y + A0a.z * B0a.z + A0a.w * B0a.w
             + A0b.x * B0b.x + A0b.y * B0b.y + A0b.z * B0b.z + A0b.w * B0b.w;
    float v1 = 0.0f;
    if (has1)
        v1 = A1a.x * B1a.x + A1a.y * B1a.y + A1a.z * B1a.z + A1a.w * B1a.w
           + A1b.x * B1b.x + A1b.y * B1b.y + A1b.z * B1b.z + A1b.w * B1b.w;

    #pragma unroll
    for (int o = 8; o > 0; o >>= 1) {
        v0 += __shfl_xor_sync(0xFFFFFFFFu, v0, o);
        v1 += __shfl_xor_sync(0xFFFFFFFFu, v1, o);
    }

    if (sub == 0) {
        __stcs(&out[e0], 1.0f / (1.0f + __expf(-v0)));
        if (has1)
            __stcs(&out[e1], 1.0f / (1.0f + __expf(-v1)));
    }
}

// ---------------------------------------------------------------------------
// Launch
// ---------------------------------------------------------------------------
#define GEMM_SMEM ((D * D + 2 * ASZ) * sizeof(float))

extern "C" void kernel_launch(void* const* d_in, const int* in_sizes, int n_in,
                              void* d_out, int out_size)
{
    int i_xin = 0, i_xout = 1, i_ei = 2, i_w = 3;

    if (n_in == 4) {
        int w_idx = -1, ei_idx = -1;
        for (int i = 0; i < 4; i++)
            if (in_sizes[i] == D * D) w_idx = i;
        int idx[3], c = 0;
        for (int i = 0; i < 4; i++) if (i != w_idx) idx[c++] = i;
        if (w_idx >= 0 && c == 3) {
            if (in_sizes[idx[0]] == in_sizes[idx[1]])      { i_xin = idx[0]; i_xout = idx[1]; ei_idx = idx[2]; }
            else if (in_sizes[idx[0]] == in_sizes[idx[2]]) { i_xin = idx[0]; i_xout = idx[2]; ei_idx = idx[1]; }
            else                                            { i_xin = idx[1]; i_xout = idx[2]; ei_idx = idx[0]; }
            i_w = w_idx; i_ei = ei_idx;
        }
    }

    const float* x_in  = (const float*)d_in[i_xin];
    const float* x_out = (const float*)d_in[i_xout];
    const void*  ei    = d_in[i_ei];
    const float* W     = (const float*)d_in[i_w];
    float*       out   = (float*)d_out;

    int n = in_sizes[i_xin] / D;
    if (n > MAX_NODES) n = MAX_NODES;
    int E = in_sizes[i_ei] / 2;

    static int smem_set = 0;
    if (!smem_set) {
        cudaFuncSetAttribute(gemm_xout_w, cudaFuncAttributeMaxDynamicSharedMemorySize,
                             (int)GEMM_SMEM);
        smem_set = 1;
    }

    gemm_xout_w<<<NSM, 512, GEMM_SMEM>>>(x_out, W, n);

    {
        long long warps = ((long long)E + 3) / 4;
        long long total_threads = warps * 32;
        int blocks = (int)((total_threads + 255) / 256);
        edge_bilinear<<<blocks, 256>>>(x_in, ei, out, E);
    }
}

// round 16
// speedup vs baseline: 2.7431x; 1.0953x over previous
#include <cuda_runtime.h>
#include <stdint.h>

#define D 128
#define MAX_NODES 100000
#define NSM 148
#define GBM 128
#define AST 129
#define ASZ (D * AST)

// 51.2 MB scratch for y = x_out @ W0
__device__ float g_y[MAX_NODES * D];

// ---------------------------------------------------------------------------
// helpers
// ---------------------------------------------------------------------------
// L2-only (bypass L1) 32B gather with evict-last residency hint
__device__ __forceinline__ void ldg_cg_el32B(const float* p, float4& lo, float4& hi) {
    unsigned long long x0, x1, x2, x3;
    asm volatile("ld.global.cg.L2::evict_last.v4.b64 {%0,%1,%2,%3}, [%4];"
                 : "=l"(x0), "=l"(x1), "=l"(x2), "=l"(x3) : "l"(p));
    lo.x = __uint_as_float((unsigned)x0); lo.y = __uint_as_float((unsigned)(x0 >> 32));
    lo.z = __uint_as_float((unsigned)x1); lo.w = __uint_as_float((unsigned)(x1 >> 32));
    hi.x = __uint_as_float((unsigned)x2); hi.y = __uint_as_float((unsigned)(x2 >> 32));
    hi.z = __uint_as_float((unsigned)x3); hi.w = __uint_as_float((unsigned)(x3 >> 32));
}
__device__ __forceinline__ void stg_el32B(float* p, unsigned long long x0,
                                          unsigned long long x1,
                                          unsigned long long x2,
                                          unsigned long long x3) {
    asm volatile("st.global.L2::evict_last.v4.b64 [%0], {%1,%2,%3,%4};"
                 :: "l"(p), "l"(x0), "l"(x1), "l"(x2), "l"(x3) : "memory");
}
__device__ __forceinline__ void cp_async4_ef(uint32_t smem_addr, const float* gptr,
                                             unsigned long long pol) {
    asm volatile("cp.async.ca.shared.global.L2::cache_hint [%0], [%1], 4, %2;"
                 :: "r"(smem_addr), "l"(gptr), "l"(pol));
}

// ---------------------------------------------------------------------------
// Persistent GEMM (R15 config, unchanged): 148 CTAs x 512 thr, W in smem,
// A 128x128 double-buffered via cp.async (evict-first policy);
// thread = 4 rows x 8 cols as 16 packed f32x2 accumulators.
// ---------------------------------------------------------------------------
__global__ void __launch_bounds__(512, 1) gemm_xout_w(
    const float* __restrict__ x_out,
    const float* __restrict__ W,
    int n)
{
    extern __shared__ float smem[];
    float* Ws = smem;
    float* As = smem + D * D;

    const int tid    = threadIdx.x;
    const int bid    = blockIdx.x;
    const int ntiles = (n + GBM - 1) / GBM;

    #pragma unroll
    for (int i = tid; i < (D * D) / 4; i += 512)
        ((float4*)Ws)[i] = ((const float4*)W)[i];

    unsigned long long pol;
    asm("createpolicy.fractional.L2::evict_first.b64 %0, 1.0;" : "=l"(pol));

    uint32_t as_base;
    asm("{ .reg .u64 t; cvta.to.shared.u64 t, %1; cvt.u32.u64 %0, t; }"
        : "=r"(as_base) : "l"(As));

    const int kS = tid & 127;
    const int rS = tid >> 7;

    if (bid < ntiles) {
        #pragma unroll
        for (int p = 0; p < 32; p++) {
            int rr = p * 4 + rS;
            int grow = bid * GBM + rr;
            if (grow >= n) grow = n - 1;
            cp_async4_ef(as_base + (uint32_t)(kS * AST + rr) * 4,
                         &x_out[(size_t)grow * D + kS], pol);
        }
        asm volatile("cp.async.commit_group;");
    }

    const int lane = tid & 31;
    const int wcg  = tid >> 5;

    int buf = 0;
    for (int t = bid; t < ntiles; t += NSM) {
        bool has_next = (t + NSM) < ntiles;
        if (has_next) {
            int tn = t + NSM;
            uint32_t dstb = as_base + (uint32_t)((buf ^ 1) * ASZ) * 4;
            #pragma unroll
            for (int p = 0; p < 32; p++) {
                int rr = p * 4 + rS;
                int grow = tn * GBM + rr;
                if (grow >= n) grow = n - 1;
                cp_async4_ef(dstb + (uint32_t)(kS * AST + rr) * 4,
                             &x_out[(size_t)grow * D + kS], pol);
            }
            asm volatile("cp.async.commit_group;");
            asm volatile("cp.async.wait_group 1;");
        } else {
            asm volatile("cp.async.wait_group 0;");
        }
        __syncthreads();

        const float* A = As + buf * ASZ;
        unsigned long long acc[16];
        #pragma unroll
        for (int j = 0; j < 16; j++) acc[j] = 0ull;

        #pragma unroll 8
        for (int kk = 0; kk < D; kk++) {
            float a0 = A[kk * AST + lane];
            float a1 = A[kk * AST + lane + 32];
            float a2 = A[kk * AST + lane + 64];
            float a3 = A[kk * AST + lane + 96];
            unsigned long long aa0, aa1, aa2, aa3;
            asm("mov.b64 %0, {%1, %1};" : "=l"(aa0) : "r"(__float_as_uint(a0)));
            asm("mov.b64 %0, {%1, %1};" : "=l"(aa1) : "r"(__float_as_uint(a1)));
            asm("mov.b64 %0, {%1, %1};" : "=l"(aa2) : "r"(__float_as_uint(a2)));
            asm("mov.b64 %0, {%1, %1};" : "=l"(aa3) : "r"(__float_as_uint(a3)));
            const ulonglong2* wp = reinterpret_cast<const ulonglong2*>(&Ws[kk * D + wcg * 8]);
            ulonglong2 u0 = wp[0];
            ulonglong2 u1 = wp[1];
            asm("fma.rn.f32x2 %0, %1, %2, %0;" : "+l"(acc[0])  : "l"(aa0), "l"(u0.x));
            asm("fma.rn.f32x2 %0, %1, %2, %0;" : "+l"(acc[1])  : "l"(aa0), "l"(u0.y));
            asm("fma.rn.f32x2 %0, %1, %2, %0;" : "+l"(acc[2])  : "l"(aa0), "l"(u1.x));
            asm("fma.rn.f32x2 %0, %1, %2, %0;" : "+l"(acc[3])  : "l"(aa0), "l"(u1.y));
            asm("fma.rn.f32x2 %0, %1, %2, %0;" : "+l"(acc[4])  : "l"(aa1), "l"(u0.x));
            asm("fma.rn.f32x2 %0, %1, %2, %0;" : "+l"(acc[5])  : "l"(aa1), "l"(u0.y));
            asm("fma.rn.f32x2 %0, %1, %2, %0;" : "+l"(acc[6])  : "l"(aa1), "l"(u1.x));
            asm("fma.rn.f32x2 %0, %1, %2, %0;" : "+l"(acc[7])  : "l"(aa1), "l"(u1.y));
            asm("fma.rn.f32x2 %0, %1, %2, %0;" : "+l"(acc[8])  : "l"(aa2), "l"(u0.x));
            asm("fma.rn.f32x2 %0, %1, %2, %0;" : "+l"(acc[9])  : "l"(aa2), "l"(u0.y));
            asm("fma.rn.f32x2 %0, %1, %2, %0;" : "+l"(acc[10]) : "l"(aa2), "l"(u1.x));
            asm("fma.rn.f32x2 %0, %1, %2, %0;" : "+l"(acc[11]) : "l"(aa2), "l"(u1.y));
            asm("fma.rn.f32x2 %0, %1, %2, %0;" : "+l"(acc[12]) : "l"(aa3), "l"(u0.x));
            asm("fma.rn.f32x2 %0, %1, %2, %0;" : "+l"(acc[13]) : "l"(aa3), "l"(u0.y));
            asm("fma.rn.f32x2 %0, %1, %2, %0;" : "+l"(acc[14]) : "l"(aa3), "l"(u1.x));
            asm("fma.rn.f32x2 %0, %1, %2, %0;" : "+l"(acc[15]) : "l"(aa3), "l"(u1.y));
        }

        #pragma unroll
        for (int q = 0; q < 4; q++) {
            int gr = t * GBM + lane + q * 32;
            if (gr < n) {
                float* dst = g_y + (size_t)gr * D + wcg * 8;
                stg_el32B(dst, acc[q * 4 + 0], acc[q * 4 + 1],
                               acc[q * 4 + 2], acc[q * 4 + 3]);
            }
        }

        __syncthreads();
        buf ^= 1;
    }
}

// ---------------------------------------------------------------------------
// Edge kernel: warp = 4 edges (two 16-lane groups x 2 edges, MLP 4/thread).
// Gathers bypass L1 (ld.global.cg) with evict-last; paired vector index
// loads; inline dtype detection; evict-first streams.
// ---------------------------------------------------------------------------
__global__ void __launch_bounds__(256) edge_bilinear(
    const float* __restrict__ x_in,
    const void* __restrict__ ei,
    float* __restrict__ out,
    int E)
{
    const uint4 w0 = __ldg((const uint4*)ei);
    const uint4 w1 = __ldg((const uint4*)ei + 1);
    const bool is32 = ((w0.y | w0.w | w1.y | w1.w) != 0u);

    const unsigned int gthread = blockIdx.x * blockDim.x + threadIdx.x;
    const int warp_id = (int)(gthread >> 5);
    const int lane = threadIdx.x & 31;
    const int half = lane >> 4;
    const int sub  = lane & 15;
    const int e0   = warp_id * 4 + half * 2;
    const int e1   = e0 + 1;
    if (e0 >= E) return;
    const bool has1 = (e1 < E);

    long long s0, d0, s1, d1;
    if (is32) {
        const int2* ps = (const int2*)((const int*)ei + e0);
        const int2* pd = (const int2*)((const int*)ei + E + e0);
        int2 sv = __ldcs(ps);
        int2 dv = __ldcs(pd);
        s0 = sv.x; s1 = sv.y; d0 = dv.x; d1 = dv.y;
    } else {
        const longlong2* ps = (const longlong2*)((const long long*)ei + e0);
        const longlong2* pd = (const longlong2*)((const long long*)ei + (long long)E + e0);
        longlong2 sv = __ldcs(ps);
        longlong2 dv = __ldcs(pd);
        s0 = sv.x; s1 = sv.y; d0 = dv.x; d1 = dv.y;
    }
    if (!has1) { s1 = s0; d1 = d0; }

    float4 A0a, A0b, B0a, B0b, A1a, A1b, B1a, B1b;
    ldg_cg_el32B(g_y  + s0 * D + sub * 8, A0a, A0b);
    ldg_cg_el32B(x_in + d0 * D + sub * 8, B0a, B0b);
    ldg_cg_el32B(g_y  + s1 * D + sub * 8, A1a, A1b);
    ldg_cg_el32B(x_in + d1 * D + sub * 8, B1a, B1b);

    float v0 = A0a.x * B0a.x + A0a.y * B0a.y + A0a.z * B0a.z + A0a.w * B0a.w
             + A0b.x * B0b.x + A0b.y * B0b.y + A0b.z * B0b.z + A0b.w * B0b.w;
    float v1 = A1a.x * B1a.x + A1a.y * B1a.y + A1a.z * B1a.z + A1a.w * B1a.w
             + A1b.x * B1b.x + A1b.y * B1b.y + A1b.z * B1b.z + A1b.w * B1b.w;

    #pragma unroll
    for (int o = 8; o > 0; o >>= 1) {
        v0 += __shfl_xor_sync(0xFFFFFFFFu, v0, o);
        v1 += __shfl_xor_sync(0xFFFFFFFFu, v1, o);
    }

    if (sub == 0) {
        __stcs(&out[e0], 1.0f / (1.0f + __expf(-v0)));
        if (has1)
            __stcs(&out[e1], 1.0f / (1.0f + __expf(-v1)));
    }
}

// ---------------------------------------------------------------------------
// Launch
// ---------------------------------------------------------------------------
#define GEMM_SMEM ((D * D + 2 * ASZ) * sizeof(float))

extern "C" void kernel_launch(void* const* d_in, const int* in_sizes, int n_in,
                              void* d_out, int out_size)
{
    int i_xin = 0, i_xout = 1, i_ei = 2, i_w = 3;

    if (n_in == 4) {
        int w_idx = -1, ei_idx = -1;
        for (int i = 0; i < 4; i++)
            if (in_sizes[i] == D * D) w_idx = i;
        int idx[3], c = 0;
        for (int i = 0; i < 4; i++) if (i != w_idx) idx[c++] = i;
        if (w_idx >= 0 && c == 3) {
            if (in_sizes[idx[0]] == in_sizes[idx[1]])      { i_xin = idx[0]; i_xout = idx[1]; ei_idx = idx[2]; }
            else if (in_sizes[idx[0]] == in_sizes[idx[2]]) { i_xin = idx[0]; i_xout = idx[2]; ei_idx = idx[1]; }
            else                                            { i_xin = idx[1]; i_xout = idx[2]; ei_idx = idx[0]; }
            i_w = w_idx; i_ei = ei_idx;
        }
    }

    const float* x_in  = (const float*)d_in[i_xin];
    const float* x_out = (const float*)d_in[i_xout];
    const void*  ei    = d_in[i_ei];
    const float* W     = (const float*)d_in[i_w];
    float*       out   = (float*)d_out;

    int n = in_sizes[i_xin] / D;
    if (n > MAX_NODES) n = MAX_NODES;
    int E = in_sizes[i_ei] / 2;

    static int smem_set = 0;
    if (!smem_set) {
        cudaFuncSetAttribute(gemm_xout_w, cudaFuncAttributeMaxDynamicSharedMemorySize,
                             (int)GEMM_SMEM);
        smem_set = 1;
    }

    gemm_xout_w<<<NSM, 512, GEMM_SMEM>>>(x_out, W, n);

    {
        long long warps = ((long long)E + 3) / 4;
        long long total_threads = warps * 32;
        int blocks = (int)((total_threads + 255) / 256);
        edge_bilinear<<<blocks, 256>>>(x_in, ei, out, E);
    }
}